// round 1
// baseline (speedup 1.0000x reference)
#include <cuda_runtime.h>
#include <cuda_bf16.h>

// Problem constants (fixed by the reference)
#define BB 8
#define TT 4096
#define DD 256
#define MM 8
#define NC 64           // number of chunks along T
#define TC (TT / NC)    // 64 timesteps per chunk

// Scratch (allocation-free rule: __device__ globals)
__device__ float g_Lend[BB * NC * MM * DD];  // per-chunk local scan endpoint (from s=0)
__device__ float g_Sin [BB * NC * MM * DD];  // per-chunk incoming state
__device__ float g_P   [BB * NC * MM];       // per-chunk decay product

// ---------------------------------------------------------------------------
// Shared helper: build alpha[TC][MM] tile in smem for chunk (b, c).
// ---------------------------------------------------------------------------
__device__ __forceinline__ void build_alpha(
    const float* __restrict__ delta, const float* __restrict__ tau,
    int b, int t0, float (*s_alpha)[MM], float* s_dt, float* s_rtau)
{
    int tid = threadIdx.x;
    if (tid < MM) s_rtau[tid] = 1.0f / tau[tid];
    if (tid < TC) {
        int gt = t0 + tid;
        float dt = 0.0f;
        if (gt > 0) {
            float d1 = delta[b * TT + gt];
            float d0 = delta[b * TT + gt - 1];
            dt = fmaxf(d1 - d0, 0.0f);
        }
        s_dt[tid] = dt;
    }
    __syncthreads();
    for (int i = tid; i < TC * MM; i += blockDim.x) {
        int t = i >> 3;       // /MM
        int m = i & (MM - 1); // %MM
        s_alpha[t][m] = __expf(-s_dt[t] * s_rtau[m]);
    }
    __syncthreads();
}

// ---------------------------------------------------------------------------
// Pass 1: per-chunk carries. grid = B*NC blocks, 256 threads (one per d).
// Each thread keeps all M states in registers; x is read once per chunk.
// ---------------------------------------------------------------------------
__global__ __launch_bounds__(256) void carry_kernel(
    const float* __restrict__ x,
    const float* __restrict__ delta,
    const float* __restrict__ tau)
{
    __shared__ float s_alpha[TC][MM];
    __shared__ float s_dt[TC];
    __shared__ float s_rtau[MM];

    int b = blockIdx.x / NC;
    int c = blockIdx.x % NC;
    int t0 = c * TC;
    int d = threadIdx.x;

    build_alpha(delta, tau, b, t0, s_alpha, s_dt, s_rtau);

    float s[MM];
#pragma unroll
    for (int m = 0; m < MM; m++) s[m] = 0.0f;

    const float* xp = x + ((size_t)b * TT + t0) * DD + d;
#pragma unroll 4
    for (int t = 0; t < TC; t++) {
        float xv = xp[(size_t)t * DD];
#pragma unroll
        for (int m = 0; m < MM; m++) {
            float a = s_alpha[t][m];
            // s = a*s + (1-a)*x  ==  fma(a, s-x, x)
            s[m] = fmaf(a, s[m] - xv, xv);
        }
    }

    size_t base = ((size_t)(b * NC + c) * MM) * DD + d;
#pragma unroll
    for (int m = 0; m < MM; m++) g_Lend[base + (size_t)m * DD] = s[m];

    // Scalar decay products (8 threads, serial over TC — negligible)
    if (threadIdx.x < MM) {
        float p = 1.0f;
        for (int t = 0; t < TC; t++) p *= s_alpha[t][threadIdx.x];
        g_P[(b * NC + c) * MM + threadIdx.x] = p;
    }
}

// ---------------------------------------------------------------------------
// Pass 2: sequential composition of chunk carries. grid = B*M blocks, 256 thr.
// ---------------------------------------------------------------------------
__global__ __launch_bounds__(256) void scan_kernel()
{
    int b = blockIdx.x / MM;
    int m = blockIdx.x % MM;
    int d = threadIdx.x;

    float s = 0.0f;
    for (int c = 0; c < NC; c++) {
        size_t idx = ((size_t)(b * NC + c) * MM + m) * DD + d;
        g_Sin[idx] = s;
        float p = g_P[(b * NC + c) * MM + m];
        s = fmaf(p, s, g_Lend[idx]);
    }
}

// ---------------------------------------------------------------------------
// Pass 3: full scan seeded with S_in, write all outputs.
// out layout [B, T, M*D]: idx = (b*T + t)*(M*D) + m*D + d  -> coalesced stores.
// ---------------------------------------------------------------------------
__global__ __launch_bounds__(256) void final_kernel(
    const float* __restrict__ x,
    const float* __restrict__ delta,
    const float* __restrict__ tau,
    float* __restrict__ out)
{
    __shared__ float s_alpha[TC][MM];
    __shared__ float s_dt[TC];
    __shared__ float s_rtau[MM];

    int b = blockIdx.x / NC;
    int c = blockIdx.x % NC;
    int t0 = c * TC;
    int d = threadIdx.x;

    build_alpha(delta, tau, b, t0, s_alpha, s_dt, s_rtau);

    float s[MM];
    size_t cbase = ((size_t)(b * NC + c) * MM) * DD + d;
#pragma unroll
    for (int m = 0; m < MM; m++) s[m] = g_Sin[cbase + (size_t)m * DD];

    const float* xp = x + ((size_t)b * TT + t0) * DD + d;
    float* op = out + ((size_t)b * TT + t0) * (MM * DD) + d;

#pragma unroll 2
    for (int t = 0; t < TC; t++) {
        float xv = xp[(size_t)t * DD];
        float* ot = op + (size_t)t * (MM * DD);
#pragma unroll
        for (int m = 0; m < MM; m++) {
            float a = s_alpha[t][m];
            s[m] = fmaf(a, s[m] - xv, xv);
            ot[(size_t)m * DD] = s[m];
        }
    }
}

// ---------------------------------------------------------------------------
extern "C" void kernel_launch(void* const* d_in, const int* in_sizes, int n_in,
                              void* d_out, int out_size)
{
    const float* x     = (const float*)d_in[0];  // [B,T,D]
    const float* delta = (const float*)d_in[1];  // [B,T]
    const float* tau   = (const float*)d_in[2];  // [M]
    float* out = (float*)d_out;                  // [B,T,M*D]

    carry_kernel<<<BB * NC, 256>>>(x, delta, tau);
    scan_kernel<<<BB * MM, 256>>>();
    final_kernel<<<BB * NC, 256>>>(x, delta, tau, out);
}